// round 1
// baseline (speedup 1.0000x reference)
#include <cuda_runtime.h>
#include <math.h>

#define NN 32
#define LL 8192
#define CO 128
#define CI1 64
#define TT 10
#define LO 4096

// ---------------- scratch (__device__ globals; no allocation) ----------------
__device__ float g_w1[(size_t)NN * CI1 * 5 * CO];          // (N, CI1*5, CO)
__device__ float g_w2[(size_t)NN * CO * 5 * CO];           // (N, CO*5, CO)
__device__ float g_y[(size_t)NN * CO * LL];                // conv output (N, CO, L) (reused)
__device__ float g_h[(size_t)NN * LL * CO];                // layer-1 activation (N, L, CO)
__device__ float g_xd[(size_t)NN * CO * LO];               // downsample raw (N, CO, LO)
__device__ float g_scale[NN * CO];
__device__ float g_shift[NN * CO];
__device__ float g_bscale[CO];
__device__ float g_bshift[CO];

__device__ __forceinline__ float mishf(float v) {
    float sp = (v > 20.f) ? v : log1pf(expf(v));
    return v * tanhf(sp);
}

// ---------------- gate + per-sample weight build ----------------
// wout layout: (N, CI*5, CO), row index = i*5+k, col = o
__global__ void gate_weights_kernel(const float* __restrict__ t,
                                    const float* __restrict__ gw,
                                    const float* __restrict__ gb,
                                    const float* __restrict__ k5,
                                    const float* __restrict__ k3,
                                    const float* __restrict__ k1,
                                    const float* __restrict__ a3,
                                    const float* __restrict__ a5,
                                    float* __restrict__ wout, int CI)
{
    int n = blockIdx.x;
    int o = threadIdx.x;   // 128 threads
    float tv[TT];
#pragma unroll
    for (int j = 0; j < TT; j++) tv[j] = t[n * TT + j];
    float g[5];
    float mx = -1e30f;
#pragma unroll
    for (int e = 0; e < 5; e++) {
        float s = gb[e * CO + o];
        const float* gwr = gw + (size_t)(e * CO + o) * TT;
#pragma unroll
        for (int j = 0; j < TT; j++) s += tv[j] * gwr[j];
        g[e] = s;
        mx = fmaxf(mx, s);
    }
    float den = 0.f;
#pragma unroll
    for (int e = 0; e < 5; e++) { g[e] = expf(g[e] - mx); den += g[e]; }
    float inv = 1.f / den;
#pragma unroll
    for (int e = 0; e < 5; e++) g[e] *= inv;
    float g3 = g[3] * (1.f / 3.f);
    float g4 = g[4] * 0.2f;

    size_t rb = (size_t)n * CI * 5;
    for (int i = 0; i < CI; i++) {
        int oi = o * CI + i;
        const float* p5 = k5 + (size_t)oi * 5;
        const float* p3 = k3 + (size_t)oi * 3;
        float c1 = k1[oi], c3v = a3[oi], c5v = a5[oi];
        float base = g4 * c5v;
        float w0 = g[0] * p5[0] + base;
        float w1 = g[0] * p5[1] + base;
        float w2 = g[0] * p5[2] + g[1] * p3[0] + g3 * c3v + base;
        float w3 = g[0] * p5[3] + g[1] * p3[1] + g3 * c3v + base;
        float w4 = g[0] * p5[4] + g[1] * p3[2] + g3 * c3v + g[2] * c1 + base;
        wout[(rb + i * 5 + 0) * CO + o] = w0;
        wout[(rb + i * 5 + 1) * CO + o] = w1;
        wout[(rb + i * 5 + 2) * CO + o] = w2;
        wout[(rb + i * 5 + 3) * CO + o] = w3;
        wout[(rb + i * 5 + 4) * CO + o] = w4;
    }
}

// ---------------- tiled causal conv: y[n,o,l] = sum_{i,k} w[n,(i*5+k),o] * x[n,l+k-4,i] ----------------
// grid (L/128, CO/32, N); block 256; dyn smem = (64*132 + 320*32)*4 = 74752 B
template <int CI>
__global__ void __launch_bounds__(256)
conv_kernel(const float* __restrict__ x, const float* __restrict__ w,
            float* __restrict__ y)
{
    constexpr int LT = 128, OT = 32;
    extern __shared__ float sm[];
    float* xs = sm;                    // [64][LT+4]
    float* ws = sm + 64 * (LT + 4);    // [320][OT]
    const int l0 = blockIdx.x * LT, o0 = blockIdx.y * OT, n = blockIdx.z;
    const int tid = threadIdx.x;
    const int tx = tid & 31;           // l-group
    const int ty = tid >> 5;           // o-group (0..7)

    float acc[4][4];
#pragma unroll
    for (int a = 0; a < 4; a++)
#pragma unroll
        for (int b = 0; b < 4; b++) acc[a][b] = 0.f;

    for (int ci0 = 0; ci0 < CI; ci0 += 64) {
        __syncthreads();
        {   // load x tile (coalesced over channel dim)
            int i = tid & 63, m0 = tid >> 6;
            const float* xb = x + (size_t)n * LL * CI + ci0 + i;
#pragma unroll
            for (int m = m0; m < LT + 4; m += 4) {
                int l = l0 - 4 + m;
                xs[i * (LT + 4) + m] = (l >= 0) ? xb[(size_t)l * CI] : 0.f;
            }
        }
        {   // load weight tile (coalesced over o)
            int oo = tid & 31, j0 = tid >> 5;
            const float* wb = w + ((size_t)n * CI * 5 + (size_t)ci0 * 5) * CO + o0 + oo;
#pragma unroll
            for (int j = j0; j < 320; j += 8)
                ws[j * OT + oo] = wb[(size_t)j * CO];
        }
        __syncthreads();
#pragma unroll 2
        for (int i = 0; i < 64; i++) {
            float4 A = *(const float4*)&xs[i * (LT + 4) + 4 * tx];
            float4 B = *(const float4*)&xs[i * (LT + 4) + 4 * tx + 4];
            float xv[8] = {A.x, A.y, A.z, A.w, B.x, B.y, B.z, B.w};
#pragma unroll
            for (int k = 0; k < 5; k++) {
                float4 W = *(const float4*)&ws[(i * 5 + k) * OT + 4 * ty];
                float wv[4] = {W.x, W.y, W.z, W.w};
#pragma unroll
                for (int oj = 0; oj < 4; oj++)
#pragma unroll
                    for (int lj = 0; lj < 4; lj++)
                        acc[oj][lj] = fmaf(wv[oj], xv[k + lj], acc[oj][lj]);
            }
        }
    }
#pragma unroll
    for (int oj = 0; oj < 4; oj++) {
        float4 v = make_float4(acc[oj][0], acc[oj][1], acc[oj][2], acc[oj][3]);
        *(float4*)&y[((size_t)(n * CO + o0 + 4 * ty + oj)) * LL + l0 + 4 * tx] = v;
    }
}

// ---------------- instance-norm stats per (n,o): scale/shift ----------------
__global__ void inorm_stats_kernel(const float* __restrict__ y,
                                   const float* __restrict__ gamma,
                                   const float* __restrict__ beta,
                                   float* __restrict__ scale,
                                   float* __restrict__ shift)
{
    int no = blockIdx.x;
    int o = no & (CO - 1);
    const float4* p = (const float4*)(y + (size_t)no * LL);
    float s = 0.f, s2 = 0.f;
    for (int i = threadIdx.x; i < LL / 4; i += 256) {
        float4 v = p[i];
        s += v.x + v.y + v.z + v.w;
        s2 += v.x * v.x + v.y * v.y + v.z * v.z + v.w * v.w;
    }
    __shared__ float rs[256], rs2[256];
    rs[threadIdx.x] = s; rs2[threadIdx.x] = s2;
    __syncthreads();
    for (int st = 128; st > 0; st >>= 1) {
        if (threadIdx.x < st) {
            rs[threadIdx.x] += rs[threadIdx.x + st];
            rs2[threadIdx.x] += rs2[threadIdx.x + st];
        }
        __syncthreads();
    }
    if (threadIdx.x == 0) {
        float mu = rs[0] * (1.f / LL);
        float var = rs2[0] * (1.f / LL) - mu * mu;
        float sc = gamma[o] * rsqrtf(var + 1e-5f);
        scale[no] = sc;
        shift[no] = beta[o] - mu * sc;
    }
}

// ---------------- norm + mish + transpose: (N,CO,L) -> (N,L,CO) ----------------
// grid (L/32, N); block 256
__global__ void norm_transpose_kernel(const float* __restrict__ y,
                                      const float* __restrict__ scale,
                                      const float* __restrict__ shift,
                                      float* __restrict__ out)
{
    __shared__ float tile[CO][33];
    __shared__ float sc[CO], sh[CO];
    int n = blockIdx.y, l0 = blockIdx.x * 32;
    int tid = threadIdx.x;
    if (tid < CO) { sc[tid] = scale[n * CO + tid]; sh[tid] = shift[n * CO + tid]; }
    __syncthreads();
    int lt = tid & 31, ob = tid >> 5;
#pragma unroll
    for (int r = 0; r < 16; r++) {
        int o = ob + 8 * r;
        float v = y[((size_t)(n * CO + o)) * LL + l0 + lt];
        tile[o][lt] = mishf(v * sc[o] + sh[o]);
    }
    __syncthreads();
    int oc = tid & 127, lb = tid >> 7;
#pragma unroll
    for (int ly = lb; ly < 32; ly += 2)
        out[((size_t)n * LL + l0 + ly) * CO + oc] = tile[oc][ly];
}

// ---------------- downsample conv (k=2, stride 2) as K=256 GEMM ----------------
// reads x_skip (N,L,CO); grid (LO/64, CO/64, N); block 256
// dyn smem = (2*128*68 + 256*64)*4 = 135168 B
__global__ void __launch_bounds__(256)
down_conv_kernel(const float* __restrict__ xs_in, const float* __restrict__ dw,
                 float* __restrict__ xd)
{
    constexpr int JT = 64, OTD = 64, PITCH = 68;
    extern __shared__ float sm[];
    float* xse = sm;                    // [128 c][PITCH j]
    float* xso = sm + 128 * PITCH;
    float* wsm = sm + 2 * 128 * PITCH;  // [256 p][64 o]
    int j0 = blockIdx.x * JT, o0 = blockIdx.y * OTD, n = blockIdx.z;
    int tid = threadIdx.x;
    {
        int c = tid & 127, r0 = tid >> 7;
        const float* base = xs_in + ((size_t)n * LL + 2 * j0) * CO + c;
        for (int j = r0; j < JT; j += 2) {
            xse[c * PITCH + j] = base[(size_t)(2 * j) * CO];
            xso[c * PITCH + j] = base[(size_t)(2 * j + 1) * CO];
        }
    }
    {
        int oo = tid & 63, p0 = tid >> 6;
        for (int p = p0; p < 256; p += 4) {
            int i = p & 127, k = p >> 7;
            wsm[p * 64 + oo] = dw[(size_t)(o0 + oo) * 256 + i * 2 + k];
        }
    }
    __syncthreads();
    int tx = tid & 15, ty = tid >> 4;
    float acc[4][4];
#pragma unroll
    for (int a = 0; a < 4; a++)
#pragma unroll
        for (int b = 0; b < 4; b++) acc[a][b] = 0.f;
    for (int c = 0; c < 128; c++) {
        float4 xe = *(const float4*)&xse[c * PITCH + 4 * tx];
        float4 xo = *(const float4*)&xso[c * PITCH + 4 * tx];
        float4 we = *(const float4*)&wsm[c * 64 + 4 * ty];
        float4 wo = *(const float4*)&wsm[(128 + c) * 64 + 4 * ty];
        float xev[4] = {xe.x, xe.y, xe.z, xe.w};
        float xov[4] = {xo.x, xo.y, xo.z, xo.w};
        float wev[4] = {we.x, we.y, we.z, we.w};
        float wov[4] = {wo.x, wo.y, wo.z, wo.w};
#pragma unroll
        for (int oj = 0; oj < 4; oj++)
#pragma unroll
            for (int jj = 0; jj < 4; jj++) {
                acc[oj][jj] = fmaf(wev[oj], xev[jj], acc[oj][jj]);
                acc[oj][jj] = fmaf(wov[oj], xov[jj], acc[oj][jj]);
            }
    }
#pragma unroll
    for (int oj = 0; oj < 4; oj++) {
        float4 v = make_float4(acc[oj][0], acc[oj][1], acc[oj][2], acc[oj][3]);
        *(float4*)&xd[((size_t)(n * CO + o0 + 4 * ty + oj)) * LO + j0 + 4 * tx] = v;
    }
}

// ---------------- batch-norm stats per channel over (n, j) ----------------
__global__ void bn_stats_kernel(const float* __restrict__ xd,
                                const float* __restrict__ dg,
                                const float* __restrict__ db,
                                float* __restrict__ bs, float* __restrict__ bb)
{
    int o = blockIdx.x;
    float s = 0.f, s2 = 0.f;
    for (int n = 0; n < NN; n++) {
        const float4* p = (const float4*)(xd + ((size_t)n * CO + o) * LO);
        for (int i = threadIdx.x; i < LO / 4; i += 256) {
            float4 v = p[i];
            s += v.x + v.y + v.z + v.w;
            s2 += v.x * v.x + v.y * v.y + v.z * v.z + v.w * v.w;
        }
    }
    __shared__ float rs[256], rs2[256];
    rs[threadIdx.x] = s; rs2[threadIdx.x] = s2;
    __syncthreads();
    for (int st = 128; st > 0; st >>= 1) {
        if (threadIdx.x < st) {
            rs[threadIdx.x] += rs[threadIdx.x + st];
            rs2[threadIdx.x] += rs2[threadIdx.x + st];
        }
        __syncthreads();
    }
    if (threadIdx.x == 0) {
        const float cnt = (float)NN * LO;
        float mu = rs[0] / cnt;
        float var = rs2[0] / cnt - mu * mu;
        float sc = dg[o] * rsqrtf(var + 1e-5f);
        bs[o] = sc;
        bb[o] = db[o] - mu * sc;
    }
}

__global__ void bn_apply_kernel(const float* __restrict__ xd,
                                const float* __restrict__ bs,
                                const float* __restrict__ bb,
                                float* __restrict__ out)
{
    size_t i4 = (size_t)blockIdx.x * 256 + threadIdx.x;
    const size_t total4 = (size_t)NN * CO * LO / 4;
    if (i4 >= total4) return;
    float4 v = ((const float4*)xd)[i4];
    int o = (int)((i4 * 4 / LO) & (CO - 1));
    float sc = bs[o], sh = bb[o];
    float4 r;
    r.x = mishf(v.x * sc + sh);
    r.y = mishf(v.y * sc + sh);
    r.z = mishf(v.z * sc + sh);
    r.w = mishf(v.w * sc + sh);
    ((float4*)out)[i4] = r;
}

// ---------------- launch ----------------
extern "C" void kernel_launch(void* const* d_in, const int* in_sizes, int n_in,
                              void* d_out, int out_size)
{
    const float* x        = (const float*)d_in[0];
    const float* t        = (const float*)d_in[1];
    const float* l1_k5    = (const float*)d_in[2];
    const float* l1_k3    = (const float*)d_in[3];
    const float* l1_k1    = (const float*)d_in[4];
    const float* l1_a3    = (const float*)d_in[5];
    const float* l1_a5    = (const float*)d_in[6];
    const float* l1_gw    = (const float*)d_in[7];
    const float* l1_gb    = (const float*)d_in[8];
    const float* l1_gamma = (const float*)d_in[9];
    const float* l1_beta  = (const float*)d_in[10];
    const float* l2_k5    = (const float*)d_in[11];
    const float* l2_k3    = (const float*)d_in[12];
    const float* l2_k1    = (const float*)d_in[13];
    const float* l2_a3    = (const float*)d_in[14];
    const float* l2_a5    = (const float*)d_in[15];
    const float* l2_gw    = (const float*)d_in[16];
    const float* l2_gb    = (const float*)d_in[17];
    const float* l2_gamma = (const float*)d_in[18];
    const float* l2_beta  = (const float*)d_in[19];
    const float* dw       = (const float*)d_in[20];
    const float* dg       = (const float*)d_in[21];
    const float* db       = (const float*)d_in[22];

    float* out      = (float*)d_out;
    float* out_xd   = out;                              // (N, CO, LO)
    float* out_skip = out + (size_t)NN * CO * LO;       // (N, L, CO)

    float *w1, *w2, *ybuf, *hbuf, *xdbuf, *scl, *shf, *bsc, *bsh;
    cudaGetSymbolAddress((void**)&w1, g_w1);
    cudaGetSymbolAddress((void**)&w2, g_w2);
    cudaGetSymbolAddress((void**)&ybuf, g_y);
    cudaGetSymbolAddress((void**)&hbuf, g_h);
    cudaGetSymbolAddress((void**)&xdbuf, g_xd);
    cudaGetSymbolAddress((void**)&scl, g_scale);
    cudaGetSymbolAddress((void**)&shf, g_shift);
    cudaGetSymbolAddress((void**)&bsc, g_bscale);
    cudaGetSymbolAddress((void**)&bsh, g_bshift);

    const int CONV_SMEM = (64 * 132 + 320 * 32) * 4;          // 74752
    const int DOWN_SMEM = (2 * 128 * 68 + 256 * 64) * 4;      // 135168
    cudaFuncSetAttribute(conv_kernel<64>,  cudaFuncAttributeMaxDynamicSharedMemorySize, CONV_SMEM);
    cudaFuncSetAttribute(conv_kernel<128>, cudaFuncAttributeMaxDynamicSharedMemorySize, CONV_SMEM);
    cudaFuncSetAttribute(down_conv_kernel, cudaFuncAttributeMaxDynamicSharedMemorySize, DOWN_SMEM);

    // layer 1
    gate_weights_kernel<<<NN, 128>>>(t, l1_gw, l1_gb, l1_k5, l1_k3, l1_k1, l1_a3, l1_a5, w1, CI1);
    conv_kernel<CI1><<<dim3(LL / 128, CO / 32, NN), 256, CONV_SMEM>>>(x, w1, ybuf);
    inorm_stats_kernel<<<NN * CO, 256>>>(ybuf, l1_gamma, l1_beta, scl, shf);
    norm_transpose_kernel<<<dim3(LL / 32, NN), 256>>>(ybuf, scl, shf, hbuf);

    // layer 2
    gate_weights_kernel<<<NN, 128>>>(t, l2_gw, l2_gb, l2_k5, l2_k3, l2_k1, l2_a3, l2_a5, w2, CO);
    conv_kernel<CO><<<dim3(LL / 128, CO / 32, NN), 256, CONV_SMEM>>>(hbuf, w2, ybuf);
    inorm_stats_kernel<<<NN * CO, 256>>>(ybuf, l2_gamma, l2_beta, scl, shf);
    norm_transpose_kernel<<<dim3(LL / 32, NN), 256>>>(ybuf, scl, shf, out_skip);

    // downsample + BN + mish
    down_conv_kernel<<<dim3(LO / 64, CO / 64, NN), 256, DOWN_SMEM>>>(out_skip, dw, xdbuf);
    bn_stats_kernel<<<CO, 256>>>(xdbuf, dg, db, bsc, bsh);
    bn_apply_kernel<<<(int)(((size_t)NN * CO * LO / 4 + 255) / 256), 256>>>(xdbuf, bsc, bsh, out_xd);
}

// round 4
// speedup vs baseline: 1.6082x; 1.6082x over previous
#include <cuda_runtime.h>
#include <cuda_bf16.h>
#include <math.h>
#include <stdint.h>

#define NN 32
#define LL 8192
#define CO 128
#define CI1 64
#define TT 10
#define LO 4096

// ---------------- scratch (__device__ globals; no allocation) ----------------
__device__ __align__(128) __nv_bfloat16 g_xh[(size_t)NN * LL * CI1];
__device__ __align__(128) __nv_bfloat16 g_xl[(size_t)NN * LL * CI1];
__device__ __align__(128) __nv_bfloat16 g_hh[(size_t)NN * LL * CO];
__device__ __align__(128) __nv_bfloat16 g_hl[(size_t)NN * LL * CO];
__device__ __align__(128) __nv_bfloat16 g_ssh[(size_t)NN * LL * CO];
__device__ __align__(128) __nv_bfloat16 g_ssl[(size_t)NN * LL * CO];
__device__ __align__(128) float g_y[(size_t)NN * CO * LL];
__device__ __align__(128) __nv_bfloat16 g_w1h[(size_t)NN * 5 * 1 * CO * 64];
__device__ __align__(128) __nv_bfloat16 g_w1l[(size_t)NN * 5 * 1 * CO * 64];
__device__ __align__(128) __nv_bfloat16 g_w2h[(size_t)NN * 5 * 2 * CO * 64];
__device__ __align__(128) __nv_bfloat16 g_w2l[(size_t)NN * 5 * 2 * CO * 64];
__device__ __align__(128) __nv_bfloat16 g_wdh[4 * CO * 64];
__device__ __align__(128) __nv_bfloat16 g_wdl[4 * CO * 64];
__device__ __align__(128) float g_xd[(size_t)NN * CO * LO];
__device__ float g_scale[NN * CO];
__device__ float g_shift[NN * CO];
__device__ float g_bscale[CO];
__device__ float g_bshift[CO];

// ---------------- small device helpers ----------------
__device__ __forceinline__ float mishf(float v) {
    float sp = (v > 20.f) ? v : log1pf(expf(v));
    return v * tanhf(sp);
}
__device__ __forceinline__ uint32_t smem_u32(const void* p) {
    uint32_t a;
    asm("{ .reg .u64 t; cvta.to.shared.u64 t, %1; cvt.u32.u64 %0, t; }" : "=r"(a) : "l"(p));
    return a;
}
__device__ __forceinline__ void cp16(uint32_t dst, const void* src) {
    asm volatile("cp.async.cg.shared.global [%0], [%1], 16;" :: "r"(dst), "l"(src));
}
__device__ __forceinline__ void cp_commit() {
    asm volatile("cp.async.commit_group;" ::: "memory");
}
template <int N>
__device__ __forceinline__ void cp_wait() {
    asm volatile("cp.async.wait_group %0;" :: "n"(N) : "memory");
}
__device__ __forceinline__ void ldsm4(uint32_t* r, uint32_t addr) {
    asm volatile("ldmatrix.sync.aligned.m8n8.x4.shared.b16 {%0,%1,%2,%3}, [%4];"
                 : "=r"(r[0]), "=r"(r[1]), "=r"(r[2]), "=r"(r[3]) : "r"(addr));
}
__device__ __forceinline__ void mma_bf16(float* d, const uint32_t* a, const uint32_t* b) {
    asm volatile("mma.sync.aligned.m16n8k16.row.col.f32.bf16.bf16.f32 "
                 "{%0,%1,%2,%3}, {%4,%5,%6,%7}, {%8,%9}, {%0,%1,%2,%3};"
                 : "+f"(d[0]), "+f"(d[1]), "+f"(d[2]), "+f"(d[3])
                 : "r"(a[0]), "r"(a[1]), "r"(a[2]), "r"(a[3]), "r"(b[0]), "r"(b[1]));
}
__device__ __forceinline__ void bf_split(float v, __nv_bfloat16& h, __nv_bfloat16& l) {
    h = __float2bfloat16_rn(v);
    l = __float2bfloat16_rn(v - __bfloat162float(h));
}

// ============================================================================
// Conv-as-GEMM with warp-level bf16 tensor MMA (3-term split for fp32 accuracy)
//   Y[n, o, l0+j] = sum_{k<NSHIFT, i<CI} W[n, o, i, k] * X[n, RS*(l0+j)+k-HALO, i]
// CTA: 512 threads, tile M=128 (o) x N=128 (j). X hi/lo tiles resident in smem;
// W streamed as [128 o][64 i] chunks (hi+lo), double-buffered cp.async.
// Pipeline order per piece: wait(p) -> barrier -> prefetch(p+1) -> MMA(p).
// The barrier before the prefetch is what makes the double buffer safe.
// ============================================================================
template <int CI, int NSHIFT, int RS, int HALO>
__global__ void __launch_bounds__(512)
mma_conv(const __nv_bfloat16* __restrict__ Xh, const __nv_bfloat16* __restrict__ Xl,
         const __nv_bfloat16* __restrict__ Wh, const __nv_bfloat16* __restrict__ Wl,
         float* __restrict__ Y, size_t x_nstride, size_t w_nstride, int outL)
{
    constexpr int NT = 128;
    constexpr int HF = CI / 64;
    constexpr int P = NSHIFT * HF;
    constexpr int XR = NT * RS + HALO;
    constexpr int XPITCH = CI * 2 + 16;      // bytes; ≡ 4 banks (mod 32) shift per row
    constexpr int WPITCH = 144;
    constexpr int WCH = 128 * WPITCH;        // one W array chunk in smem
    constexpr int XT = XR * XPITCH;
    constexpr int SEGR = CI / 8;             // 16B segments per X row

    extern __shared__ char sm[];
    const uint32_t base = smem_u32(sm);
    const uint32_t xh_s = base, xl_s = base + XT;
    const uint32_t w_s = base + 2 * XT;      // buffers: [buf][Wh | Wl]

    const int tid = threadIdx.x;
    const int n = blockIdx.y;
    const int l0 = blockIdx.x * NT;

    if (HALO > 0 && blockIdx.x == 0) {
        const uint4 z = make_uint4(0, 0, 0, 0);
        for (int s = tid; s < HALO * SEGR; s += 512) {
            int r = s / SEGR, c = s % SEGR;
            *(uint4*)(sm + r * XPITCH + c * 16) = z;
            *(uint4*)(sm + XT + r * XPITCH + c * 16) = z;
        }
    }
    {   // X hi/lo tiles
        const __nv_bfloat16* gh = Xh + (size_t)n * x_nstride;
        const __nv_bfloat16* gl_ = Xl + (size_t)n * x_nstride;
        for (int s = tid; s < XR * SEGR; s += 512) {
            int r = s / SEGR, c = s % SEGR;
            long l = (long)l0 * RS - HALO + r;
            if (l >= 0) {
                size_t go = (size_t)l * CI + (size_t)c * 8;
                cp16(xh_s + r * XPITCH + c * 16, gh + go);
                cp16(xl_s + r * XPITCH + c * 16, gl_ + go);
            }
        }
    }
    {   // W piece 0
        const __nv_bfloat16* ph = Wh + (size_t)n * w_nstride;
        const __nv_bfloat16* pl = Wl + (size_t)n * w_nstride;
        for (int s = tid; s < 1024; s += 512) {
            int r = s >> 3, c = s & 7;
            cp16(w_s + r * WPITCH + c * 16, ph + r * 64 + c * 8);
            cp16(w_s + WCH + r * WPITCH + c * 16, pl + r * 64 + c * 8);
        }
    }
    cp_commit();

    const int warp = tid >> 5, lane = tid & 31;
    const int o0w = (warp >> 2) * 32, n0w = (warp & 3) * 32;
    const int a_row = (lane & 7) + ((lane >> 3) & 1) * 8;
    const int a_csh = (lane >> 4) * 8;
    const int b_jj = (lane & 7) + ((lane >> 4) << 3);
    const int b_csh = ((lane >> 3) & 1) * 8;

    float acc[2][4][4];
#pragma unroll
    for (int mi = 0; mi < 2; mi++)
#pragma unroll
        for (int nf = 0; nf < 4; nf++)
#pragma unroll
            for (int q = 0; q < 4; q++) acc[mi][nf][q] = 0.f;

    for (int p = 0; p < P; p++) {
        // piece p (and X on p==0) resident after this wait
        cp_wait<0>();
        // barrier: every thread has finished reading buffer (p+1)&1 (= piece p-1)
        __syncthreads();
        if (p + 1 < P) {
            const int b = (p + 1) & 1;
            const __nv_bfloat16* ph = Wh + (size_t)n * w_nstride + (size_t)(p + 1) * 8192;
            const __nv_bfloat16* pl = Wl + (size_t)n * w_nstride + (size_t)(p + 1) * 8192;
            for (int s = tid; s < 1024; s += 512) {
                int r = s >> 3, c = s & 7;
                cp16(w_s + b * 2 * WCH + r * WPITCH + c * 16, ph + r * 64 + c * 8);
                cp16(w_s + b * 2 * WCH + WCH + r * WPITCH + c * 16, pl + r * 64 + c * 8);
            }
            cp_commit();
        }

        const int k = p / HF, hf = p % HF;
        const uint32_t wh_b = w_s + (uint32_t)(p & 1) * (2 * WCH);
        const uint32_t wl_b = wh_b + WCH;

#pragma unroll
        for (int i16 = 0; i16 < 4; i16++) {
            const int i0 = i16 * 16;
            uint32_t Ah[2][4], Al[2][4], Bh[2][4], Bl[2][4];
#pragma unroll
            for (int mi = 0; mi < 2; mi++) {
                uint32_t ao = (uint32_t)((o0w + a_row + mi * 16) * WPITCH + (i0 + a_csh) * 2);
                ldsm4(Ah[mi], wh_b + ao);
                ldsm4(Al[mi], wl_b + ao);
            }
            const int xcol = (hf * 64 + i0 + b_csh) * 2;
#pragma unroll
            for (int nb = 0; nb < 2; nb++) {
                uint32_t xo = (uint32_t)((RS * (n0w + nb * 16 + b_jj) + k) * XPITCH + xcol);
                ldsm4(Bh[nb], xh_s + xo);
                ldsm4(Bl[nb], xl_s + xo);
            }
#pragma unroll
            for (int mi = 0; mi < 2; mi++)
#pragma unroll
                for (int nf = 0; nf < 4; nf++) {
                    const uint32_t* bh = &Bh[nf >> 1][(nf & 1) * 2];
                    const uint32_t* bl = &Bl[nf >> 1][(nf & 1) * 2];
                    mma_bf16(acc[mi][nf], Ah[mi], bh);
                    mma_bf16(acc[mi][nf], Al[mi], bh);
                    mma_bf16(acc[mi][nf], Ah[mi], bl);
                }
        }
    }

    // epilogue: fp32 to (n, o, l)
    const int g = lane >> 2, tg = lane & 3;
#pragma unroll
    for (int mi = 0; mi < 2; mi++) {
        const int o = o0w + mi * 16 + g;
        float* row0 = Y + ((size_t)(n * CO + o)) * outL + l0 + n0w;
        float* row1 = row0 + (size_t)8 * outL;
#pragma unroll
        for (int nf = 0; nf < 4; nf++) {
            int c = nf * 8 + tg * 2;
            *(float2*)(row0 + c) = make_float2(acc[mi][nf][0], acc[mi][nf][1]);
            *(float2*)(row1 + c) = make_float2(acc[mi][nf][2], acc[mi][nf][3]);
        }
    }
}

// ---------------- fp32 -> bf16 hi/lo split ----------------
__global__ void split_x_kernel(const float* __restrict__ src,
                               __nv_bfloat16* __restrict__ hi,
                               __nv_bfloat16* __restrict__ lo, size_t count4)
{
    size_t i = (size_t)blockIdx.x * 256 + threadIdx.x;
    if (i >= count4) return;
    float4 v = ((const float4*)src)[i];
    __nv_bfloat16 h0, h1, h2, h3, l0_, l1_, l2_, l3_;
    bf_split(v.x, h0, l0_); bf_split(v.y, h1, l1_);
    bf_split(v.z, h2, l2_); bf_split(v.w, h3, l3_);
    ((__nv_bfloat162*)hi)[2 * i]     = __nv_bfloat162(h0, h1);
    ((__nv_bfloat162*)hi)[2 * i + 1] = __nv_bfloat162(h2, h3);
    ((__nv_bfloat162*)lo)[2 * i]     = __nv_bfloat162(l0_, l1_);
    ((__nv_bfloat162*)lo)[2 * i + 1] = __nv_bfloat162(l2_, l3_);
}

// ---------------- gate + per-sample weights (bf16 hi/lo) ----------------
// layout: (((n*5 + k)*HF + hf)*128 + o)*64 + ii
__global__ void gate_weights_kernel(const float* __restrict__ t,
                                    const float* __restrict__ gw,
                                    const float* __restrict__ gb,
                                    const float* __restrict__ k5,
                                    const float* __restrict__ k3,
                                    const float* __restrict__ k1,
                                    const float* __restrict__ a3,
                                    const float* __restrict__ a5,
                                    __nv_bfloat16* __restrict__ wh,
                                    __nv_bfloat16* __restrict__ wl, int CI)
{
    int n = blockIdx.x;
    int o = threadIdx.x;
    int HF = CI >> 6;
    float tv[TT];
#pragma unroll
    for (int j = 0; j < TT; j++) tv[j] = t[n * TT + j];
    float g[5];
    float mx = -1e30f;
#pragma unroll
    for (int e = 0; e < 5; e++) {
        float s = gb[e * CO + o];
        const float* gwr = gw + (size_t)(e * CO + o) * TT;
#pragma unroll
        for (int j = 0; j < TT; j++) s += tv[j] * gwr[j];
        g[e] = s;
        mx = fmaxf(mx, s);
    }
    float den = 0.f;
#pragma unroll
    for (int e = 0; e < 5; e++) { g[e] = expf(g[e] - mx); den += g[e]; }
    float inv = 1.f / den;
#pragma unroll
    for (int e = 0; e < 5; e++) g[e] *= inv;
    float g3 = g[3] * (1.f / 3.f);
    float g4 = g[4] * 0.2f;

    for (int i = 0; i < CI; i++) {
        int oi = o * CI + i;
        const float* p5 = k5 + (size_t)oi * 5;
        const float* p3 = k3 + (size_t)oi * 3;
        float c1 = k1[oi], c3v = a3[oi], c5v = a5[oi];
        float bse = g4 * c5v;
        float wv[5];
        wv[0] = g[0] * p5[0] + bse;
        wv[1] = g[0] * p5[1] + bse;
        wv[2] = g[0] * p5[2] + g[1] * p3[0] + g3 * c3v + bse;
        wv[3] = g[0] * p5[3] + g[1] * p3[1] + g3 * c3v + bse;
        wv[4] = g[0] * p5[4] + g[1] * p3[2] + g3 * c3v + g[2] * c1 + bse;
        int hf = i >> 6, ii = i & 63;
#pragma unroll
        for (int k = 0; k < 5; k++) {
            __nv_bfloat16 h, l;
            bf_split(wv[k], h, l);
            size_t idx = ((((size_t)n * 5 + k) * HF + hf) * 128 + o) * 64 + ii;
            wh[idx] = h;
            wl[idx] = l;
        }
    }
}

// ---------------- downsample weight reorder + split ----------------
// out layout: ((kk*2 + hf)*128 + o)*64 + ii, value = dw[o][hf*64+ii][kk]
__global__ void split_dw_kernel(const float* __restrict__ dw,
                                __nv_bfloat16* __restrict__ wdh,
                                __nv_bfloat16* __restrict__ wdl)
{
    int idx = blockIdx.x * 256 + threadIdx.x;   // CO * 256
    if (idx >= CO * 256) return;
    int o = idx >> 8, r = idx & 255;
    int kk = r >> 7, ifull = r & 127;
    float v = dw[(size_t)o * 256 + ifull * 2 + kk];
    __nv_bfloat16 h, l;
    bf_split(v, h, l);
    size_t out = (((size_t)kk * 2 + (ifull >> 6)) * 128 + o) * 64 + (ifull & 63);
    wdh[out] = h;
    wdl[out] = l;
}

// ---------------- instance-norm stats per (n,o) ----------------
__global__ void inorm_stats_kernel(const float* __restrict__ y,
                                   const float* __restrict__ gamma,
                                   const float* __restrict__ beta,
                                   float* __restrict__ scale,
                                   float* __restrict__ shift)
{
    int no = blockIdx.x;
    int o = no & (CO - 1);
    const float4* p = (const float4*)(y + (size_t)no * LL);
    float s = 0.f, s2 = 0.f;
    for (int i = threadIdx.x; i < LL / 4; i += 256) {
        float4 v = p[i];
        s += v.x + v.y + v.z + v.w;
        s2 += v.x * v.x + v.y * v.y + v.z * v.z + v.w * v.w;
    }
    __shared__ float rs[256], rs2[256];
    rs[threadIdx.x] = s; rs2[threadIdx.x] = s2;
    __syncthreads();
    for (int st = 128; st > 0; st >>= 1) {
        if (threadIdx.x < st) {
            rs[threadIdx.x] += rs[threadIdx.x + st];
            rs2[threadIdx.x] += rs2[threadIdx.x + st];
        }
        __syncthreads();
    }
    if (threadIdx.x == 0) {
        float mu = rs[0] * (1.f / LL);
        float var = rs2[0] * (1.f / LL) - mu * mu;
        float sc = gamma[o] * rsqrtf(var + 1e-5f);
        scale[no] = sc;
        shift[no] = beta[o] - mu * sc;
    }
}

// ---------------- norm + mish + transpose (+ bf16 hi/lo outputs) ----------------
__global__ void norm_transpose_kernel(const float* __restrict__ y,
                                      const float* __restrict__ scale,
                                      const float* __restrict__ shift,
                                      float* __restrict__ out_full,
                                      __nv_bfloat16* __restrict__ out_hi,
                                      __nv_bfloat16* __restrict__ out_lo)
{
    __shared__ float tile[CO][33];
    __shared__ float sc[CO], sh[CO];
    int n = blockIdx.y, l0 = blockIdx.x * 32;
    int tid = threadIdx.x;
    if (tid < CO) { sc[tid] = scale[n * CO + tid]; sh[tid] = shift[n * CO + tid]; }
    __syncthreads();
    int lt = tid & 31, ob = tid >> 5;
#pragma unroll
    for (int r = 0; r < 16; r++) {
        int o = ob + 8 * r;
        float v = y[((size_t)(n * CO + o)) * LL + l0 + lt];
        tile[o][lt] = mishf(v * sc[o] + sh[o]);
    }
    __syncthreads();
    int oc = tid & 127, lb = tid >> 7;
#pragma unroll
    for (int ly = lb; ly < 32; ly += 2) {
        size_t idx = ((size_t)n * LL + l0 + ly) * CO + oc;
        float v = tile[oc][ly];
        if (out_full) out_full[idx] = v;
        __nv_bfloat16 h, l;
        bf_split(v, h, l);
        out_hi[idx] = h;
        out_lo[idx] = l;
    }
}

// ---------------- batch-norm stats + apply ----------------
__global__ void bn_stats_kernel(const float* __restrict__ xd,
                                const float* __restrict__ dg,
                                const float* __restrict__ db,
                                float* __restrict__ bs, float* __restrict__ bb)
{
    int o = blockIdx.x;
    float s = 0.f, s2 = 0.f;
    for (int n = 0; n < NN; n++) {
        const float4* p = (const float4*)(xd + ((size_t)n * CO + o) * LO);
        for (int i = threadIdx.x; i < LO / 4; i += 256) {
            float4 v = p[i];
            s += v.x + v.y + v.z + v.w;
            s2 += v.x * v.x + v.y * v.y + v.z * v.z + v.w * v.w;
        }
    }
    __shared__ float rs[256], rs2[256];
    rs[threadIdx.x] = s; rs2[threadIdx.x] = s2;
    __syncthreads();
    for (int st = 128; st > 0; st >>= 1) {
        if (threadIdx.x < st) {
            rs[threadIdx.x] += rs[threadIdx.x + st];
            rs2[threadIdx.x] += rs2[threadIdx.x + st];
        }
        __syncthreads();
    }
    if (threadIdx.x == 0) {
        const float cnt = (float)NN * LO;
        float mu = rs[0] / cnt;
        float var = rs2[0] / cnt - mu * mu;
        float sc = dg[o] * rsqrtf(var + 1e-5f);
        bs[o] = sc;
        bb[o] = db[o] - mu * sc;
    }
}

__global__ void bn_apply_kernel(const float* __restrict__ xd,
                                const float* __restrict__ bs,
                                const float* __restrict__ bb,
                                float* __restrict__ out)
{
    size_t i4 = (size_t)blockIdx.x * 256 + threadIdx.x;
    const size_t total4 = (size_t)NN * CO * LO / 4;
    if (i4 >= total4) return;
    float4 v = ((const float4*)xd)[i4];
    int o = (int)((i4 * 4 / LO) & (CO - 1));
    float sc = bs[o], sh = bb[o];
    float4 r;
    r.x = mishf(v.x * sc + sh);
    r.y = mishf(v.y * sc + sh);
    r.z = mishf(v.z * sc + sh);
    r.w = mishf(v.w * sc + sh);
    ((float4*)out)[i4] = r;
}

// ---------------- launch ----------------
extern "C" void kernel_launch(void* const* d_in, const int* in_sizes, int n_in,
                              void* d_out, int out_size)
{
    const float* x        = (const float*)d_in[0];
    const float* t        = (const float*)d_in[1];
    const float* l1_k5    = (const float*)d_in[2];
    const float* l1_k3    = (const float*)d_in[3];
    const float* l1_k1    = (const float*)d_in[4];
    const float* l1_a3    = (const float*)d_in[5];
    const float* l1_a5    = (const float*)d_in[6];
    const float* l1_gw    = (const float*)d_in[7];
    const float* l1_gb    = (const float*)d_in[8];
    const float* l1_gamma = (const float*)d_in[9];
    const float* l1_beta  = (const float*)d_in[10];
    const float* l2_k5    = (const float*)d_in[11];
    const float* l2_k3    = (const float*)d_in[12];
    const float* l2_k1    = (const float*)d_in[13];
    const float* l2_a3    = (const float*)d_in[14];
    const float* l2_a5    = (const float*)d_in[15];
    const float* l2_gw    = (const float*)d_in[16];
    const float* l2_gb    = (const float*)d_in[17];
    const float* l2_gamma = (const float*)d_in[18];
    const float* l2_beta  = (const float*)d_in[19];
    const float* dw       = (const float*)d_in[20];
    const float* dg       = (const float*)d_in[21];
    const float* db       = (const float*)d_in[22];

    float* out      = (float*)d_out;
    float* out_xd   = out;
    float* out_skip = out + (size_t)NN * CO * LO;

    __nv_bfloat16 *xh, *xl, *hh, *hl, *ssh, *ssl, *w1h, *w1l, *w2h, *w2l, *wdh, *wdl;
    float *ybuf, *xdbuf, *scl, *shf, *bsc, *bsh;
    cudaGetSymbolAddress((void**)&xh, g_xh);
    cudaGetSymbolAddress((void**)&xl, g_xl);
    cudaGetSymbolAddress((void**)&hh, g_hh);
    cudaGetSymbolAddress((void**)&hl, g_hl);
    cudaGetSymbolAddress((void**)&ssh, g_ssh);
    cudaGetSymbolAddress((void**)&ssl, g_ssl);
    cudaGetSymbolAddress((void**)&ybuf, g_y);
    cudaGetSymbolAddress((void**)&w1h, g_w1h);
    cudaGetSymbolAddress((void**)&w1l, g_w1l);
    cudaGetSymbolAddress((void**)&w2h, g_w2h);
    cudaGetSymbolAddress((void**)&w2l, g_w2l);
    cudaGetSymbolAddress((void**)&wdh, g_wdh);
    cudaGetSymbolAddress((void**)&wdl, g_wdl);
    cudaGetSymbolAddress((void**)&xdbuf, g_xd);
    cudaGetSymbolAddress((void**)&scl, g_scale);
    cudaGetSymbolAddress((void**)&shf, g_shift);
    cudaGetSymbolAddress((void**)&bsc, g_bscale);
    cudaGetSymbolAddress((void**)&bsh, g_bshift);

    // smem sizes
    const int SM1 = 2 * (132 * 144) + 4 * (128 * 144);   // 111744
    const int SM2 = 2 * (132 * 272) + 4 * (128 * 144);   // 145536
    const int SMD = 2 * (256 * 272) + 4 * (128 * 144);   // 212992
    cudaFuncSetAttribute((const void*)mma_conv<64, 5, 1, 4>,
                         cudaFuncAttributeMaxDynamicSharedMemorySize, SM1);
    cudaFuncSetAttribute((const void*)mma_conv<128, 5, 1, 4>,
                         cudaFuncAttributeMaxDynamicSharedMemorySize, SM2);
    cudaFuncSetAttribute((const void*)mma_conv<128, 2, 2, 0>,
                         cudaFuncAttributeMaxDynamicSharedMemorySize, SMD);

    // x -> bf16 hi/lo
    {
        size_t c4 = (size_t)NN * LL * CI1 / 4;
        split_x_kernel<<<(int)((c4 + 255) / 256), 256>>>(x, xh, xl, c4);
    }

    // layer 1
    gate_weights_kernel<<<NN, 128>>>(t, l1_gw, l1_gb, l1_k5, l1_k3, l1_k1, l1_a3, l1_a5,
                                     w1h, w1l, CI1);
    mma_conv<64, 5, 1, 4><<<dim3(LL / 128, NN), 512, SM1>>>(
        xh, xl, w1h, w1l, ybuf, (size_t)LL * CI1, (size_t)5 * 1 * CO * 64, LL);
    inorm_stats_kernel<<<NN * CO, 256>>>(ybuf, l1_gamma, l1_beta, scl, shf);
    norm_transpose_kernel<<<dim3(LL / 32, NN), 256>>>(ybuf, scl, shf, nullptr, hh, hl);

    // layer 2
    gate_weights_kernel<<<NN, 128>>>(t, l2_gw, l2_gb, l2_k5, l2_k3, l2_k1, l2_a3, l2_a5,
                                     w2h, w2l, CO);
    mma_conv<128, 5, 1, 4><<<dim3(LL / 128, NN), 512, SM2>>>(
        hh, hl, w2h, w2l, ybuf, (size_t)LL * CO, (size_t)5 * 2 * CO * 64, LL);
    inorm_stats_kernel<<<NN * CO, 256>>>(ybuf, l2_gamma, l2_beta, scl, shf);
    norm_transpose_kernel<<<dim3(LL / 32, NN), 256>>>(ybuf, scl, shf, out_skip, ssh, ssl);

    // downsample + BN + mish
    split_dw_kernel<<<(CO * 256 + 255) / 256, 256>>>(dw, wdh, wdl);
    mma_conv<128, 2, 2, 0><<<dim3(LO / 128, NN), 512, SMD>>>(
        ssh, ssl, wdh, wdl, xdbuf, (size_t)LL * CO, 0, LO);
    bn_stats_kernel<<<CO, 256>>>(xdbuf, dg, db, bsc, bsh);
    bn_apply_kernel<<<(int)(((size_t)NN * CO * LO / 4 + 255) / 256), 256>>>(xdbuf, bsc, bsh, out_xd);
}

// round 5
// speedup vs baseline: 2.4496x; 1.5232x over previous
#include <cuda_runtime.h>
#include <cuda_bf16.h>
#include <math.h>
#include <stdint.h>

#define NN 32
#define LL 8192
#define CO 128
#define CI1 64
#define TT 10
#define LO 4096

// ---------------- scratch (__device__ globals; no allocation) ----------------
__device__ __align__(128) __nv_bfloat16 g_xh[(size_t)NN * LL * CI1];
__device__ __align__(128) __nv_bfloat16 g_xl[(size_t)NN * LL * CI1];
__device__ __align__(128) __nv_bfloat16 g_hh[(size_t)NN * LL * CO];
__device__ __align__(128) __nv_bfloat16 g_hl[(size_t)NN * LL * CO];
__device__ __align__(128) __nv_bfloat16 g_ssh[(size_t)NN * LL * CO];
__device__ __align__(128) __nv_bfloat16 g_ssl[(size_t)NN * LL * CO];
__device__ __align__(128) float g_y[(size_t)NN * CO * LL];
__device__ __align__(128) __nv_bfloat16 g_w1h[(size_t)NN * 5 * 1 * CO * 64];
__device__ __align__(128) __nv_bfloat16 g_w1l[(size_t)NN * 5 * 1 * CO * 64];
__device__ __align__(128) __nv_bfloat16 g_w2h[(size_t)NN * 5 * 2 * CO * 64];
__device__ __align__(128) __nv_bfloat16 g_w2l[(size_t)NN * 5 * 2 * CO * 64];
__device__ __align__(128) __nv_bfloat16 g_wdh[4 * CO * 64];
__device__ __align__(128) __nv_bfloat16 g_wdl[4 * CO * 64];
__device__ __align__(128) float g_xd[(size_t)NN * CO * LO];
__device__ float g_s1[NN * CO];      // conv stats accumulators (sum)
__device__ float g_s2[NN * CO];      // conv stats accumulators (sumsq)
__device__ float g_b1[CO];           // bn stats accumulators
__device__ float g_b2[CO];
__device__ float g_scale[NN * CO];
__device__ float g_shift[NN * CO];
__device__ float g_bscale[CO];
__device__ float g_bshift[CO];

// ---------------- small device helpers ----------------
__device__ __forceinline__ float mishf(float v) {
    float sp = (v > 20.f) ? v : log1pf(expf(v));
    return v * tanhf(sp);
}
__device__ __forceinline__ uint32_t smem_u32(const void* p) {
    uint32_t a;
    asm("{ .reg .u64 t; cvta.to.shared.u64 t, %1; cvt.u32.u64 %0, t; }" : "=r"(a) : "l"(p));
    return a;
}
__device__ __forceinline__ void cp16(uint32_t dst, const void* src) {
    asm volatile("cp.async.cg.shared.global [%0], [%1], 16;" :: "r"(dst), "l"(src));
}
__device__ __forceinline__ void cp_commit() {
    asm volatile("cp.async.commit_group;" ::: "memory");
}
template <int N>
__device__ __forceinline__ void cp_wait() {
    asm volatile("cp.async.wait_group %0;" :: "n"(N) : "memory");
}
__device__ __forceinline__ void ldsm4(uint32_t* r, uint32_t addr) {
    asm volatile("ldmatrix.sync.aligned.m8n8.x4.shared.b16 {%0,%1,%2,%3}, [%4];"
                 : "=r"(r[0]), "=r"(r[1]), "=r"(r[2]), "=r"(r[3]) : "r"(addr));
}
__device__ __forceinline__ void mma_bf16(float* d, const uint32_t* a, const uint32_t* b) {
    asm volatile("mma.sync.aligned.m16n8k16.row.col.f32.bf16.bf16.f32 "
                 "{%0,%1,%2,%3}, {%4,%5,%6,%7}, {%8,%9}, {%0,%1,%2,%3};"
                 : "+f"(d[0]), "+f"(d[1]), "+f"(d[2]), "+f"(d[3])
                 : "r"(a[0]), "r"(a[1]), "r"(a[2]), "r"(a[3]), "r"(b[0]), "r"(b[1]));
}
__device__ __forceinline__ void bf_split(float v, __nv_bfloat16& h, __nv_bfloat16& l) {
    h = __float2bfloat16_rn(v);
    l = __float2bfloat16_rn(v - __bfloat162float(h));
}

// ============================================================================
// Conv-as-GEMM, warp-level bf16 MMA, 3-term split. Fused stats in epilogue.
//   Y[n, o, l0+j] = sum_{k<NSHIFT, i<CI} W[n,o,i,k] * X[n, RS*(l0+j)+k-HALO, i]
// CTA 512 threads, tile M=128 (o) x NT (l). Per-piece: wait -> barrier ->
// prefetch(p+1) -> MMA(p). Stats: per-thread sums from accs, quad shuffle
// reduce, atomicAdd into s1/s2 (zeroed by an earlier kernel in the stream).
// ============================================================================
template <int CI, int NSHIFT, int RS, int HALO, int NT, bool PER_N_STATS>
__global__ void __launch_bounds__(512)
mma_conv(const __nv_bfloat16* __restrict__ Xh, const __nv_bfloat16* __restrict__ Xl,
         const __nv_bfloat16* __restrict__ Wh, const __nv_bfloat16* __restrict__ Wl,
         float* __restrict__ Y, float* __restrict__ S1, float* __restrict__ S2,
         size_t x_nstride, size_t w_nstride, int outL)
{
    constexpr int HF = CI / 64;
    constexpr int P = NSHIFT * HF;
    constexpr int XR = NT * RS + HALO;
    constexpr int XPITCH = CI * 2 + 16;      // bytes; row step ≡ 4 banks (mod 32)
    constexpr int WPITCH = 144;
    constexpr int WCH = 128 * WPITCH;
    constexpr int XT = XR * XPITCH;
    constexpr int SEGR = CI / 8;
    constexpr int NB = NT / 64;              // 16-col B blocks per warp
    constexpr int NFR = 2 * NB;              // m16n8 fragments per warp

    extern __shared__ char sm[];
    const uint32_t base = smem_u32(sm);
    const uint32_t xh_s = base, xl_s = base + XT;
    const uint32_t w_s = base + 2 * XT;

    const int tid = threadIdx.x;
    const int n = blockIdx.y;
    const int l0 = blockIdx.x * NT;

    if (HALO > 0 && blockIdx.x == 0) {
        const uint4 z = make_uint4(0, 0, 0, 0);
        for (int s = tid; s < HALO * SEGR; s += 512) {
            int r = s / SEGR, c = s % SEGR;
            *(uint4*)(sm + r * XPITCH + c * 16) = z;
            *(uint4*)(sm + XT + r * XPITCH + c * 16) = z;
        }
    }
    {   // X hi/lo tiles
        const __nv_bfloat16* gh = Xh + (size_t)n * x_nstride;
        const __nv_bfloat16* gl_ = Xl + (size_t)n * x_nstride;
        for (int s = tid; s < XR * SEGR; s += 512) {
            int r = s / SEGR, c = s % SEGR;
            long l = (long)l0 * RS - HALO + r;
            if (l >= 0) {
                size_t go = (size_t)l * CI + (size_t)c * 8;
                cp16(xh_s + r * XPITCH + c * 16, gh + go);
                cp16(xl_s + r * XPITCH + c * 16, gl_ + go);
            }
        }
    }
    {   // W piece 0
        const __nv_bfloat16* ph = Wh + (size_t)n * w_nstride;
        const __nv_bfloat16* pl = Wl + (size_t)n * w_nstride;
        for (int s = tid; s < 1024; s += 512) {
            int r = s >> 3, c = s & 7;
            cp16(w_s + r * WPITCH + c * 16, ph + r * 64 + c * 8);
            cp16(w_s + WCH + r * WPITCH + c * 16, pl + r * 64 + c * 8);
        }
    }
    cp_commit();

    const int warp = tid >> 5, lane = tid & 31;
    const int o0w = (warp >> 2) * 32, n0w = (warp & 3) * (NT / 4);
    const int a_row = (lane & 7) + ((lane >> 3) & 1) * 8;
    const int a_csh = (lane >> 4) * 8;
    const int b_jj = (lane & 7) + ((lane >> 4) << 3);
    const int b_csh = ((lane >> 3) & 1) * 8;

    float acc[2][NFR][4];
#pragma unroll
    for (int mi = 0; mi < 2; mi++)
#pragma unroll
        for (int nf = 0; nf < NFR; nf++)
#pragma unroll
            for (int q = 0; q < 4; q++) acc[mi][nf][q] = 0.f;

    for (int p = 0; p < P; p++) {
        cp_wait<0>();
        __syncthreads();   // everyone done reading buffer (p+1)&1 (= piece p-1)
        if (p + 1 < P) {
            const int b = (p + 1) & 1;
            const __nv_bfloat16* ph = Wh + (size_t)n * w_nstride + (size_t)(p + 1) * 8192;
            const __nv_bfloat16* pl = Wl + (size_t)n * w_nstride + (size_t)(p + 1) * 8192;
            for (int s = tid; s < 1024; s += 512) {
                int r = s >> 3, c = s & 7;
                cp16(w_s + b * 2 * WCH + r * WPITCH + c * 16, ph + r * 64 + c * 8);
                cp16(w_s + b * 2 * WCH + WCH + r * WPITCH + c * 16, pl + r * 64 + c * 8);
            }
            cp_commit();
        }

        const int k = p / HF, hf = p % HF;
        const uint32_t wh_b = w_s + (uint32_t)(p & 1) * (2 * WCH);
        const uint32_t wl_b = wh_b + WCH;

#pragma unroll
        for (int i16 = 0; i16 < 4; i16++) {
            const int i0 = i16 * 16;
            uint32_t Ah[2][4], Al[2][4];
#pragma unroll
            for (int mi = 0; mi < 2; mi++) {
                uint32_t ao = (uint32_t)((o0w + a_row + mi * 16) * WPITCH + (i0 + a_csh) * 2);
                ldsm4(Ah[mi], wh_b + ao);
                ldsm4(Al[mi], wl_b + ao);
            }
            const int xcol = (hf * 64 + i0 + b_csh) * 2;
#pragma unroll
            for (int nb = 0; nb < NB; nb++) {
                uint32_t Bh[4], Bl[4];
                uint32_t xo = (uint32_t)((RS * (n0w + nb * 16 + b_jj) + k) * XPITCH + xcol);
                ldsm4(Bh, xh_s + xo);
                ldsm4(Bl, xl_s + xo);
#pragma unroll
                for (int mi = 0; mi < 2; mi++)
#pragma unroll
                    for (int hl = 0; hl < 2; hl++) {
                        float* d = acc[mi][nb * 2 + hl];
                        mma_bf16(d, Ah[mi], &Bh[hl * 2]);
                        mma_bf16(d, Al[mi], &Bh[hl * 2]);
                        mma_bf16(d, Ah[mi], &Bl[hl * 2]);
                    }
            }
        }
    }

    // ---------------- epilogue: store + fused stats ----------------
    const int g = lane >> 2, tg = lane & 3;
#pragma unroll
    for (int mi = 0; mi < 2; mi++) {
        const int o = o0w + mi * 16 + g;
        float* row0 = Y + ((size_t)(n * CO + o)) * outL + l0 + n0w;
        float* row1 = row0 + (size_t)8 * outL;
#pragma unroll
        for (int nf = 0; nf < NFR; nf++) {
            int c = nf * 8 + tg * 2;
            *(float2*)(row0 + c) = make_float2(acc[mi][nf][0], acc[mi][nf][1]);
            *(float2*)(row1 + c) = make_float2(acc[mi][nf][2], acc[mi][nf][3]);
        }
    }
    // stats: per-thread sums over its columns, for 4 o-rows
    float ts[4], tq[4];
#pragma unroll
    for (int r = 0; r < 4; r++) { ts[r] = 0.f; tq[r] = 0.f; }
#pragma unroll
    for (int mi = 0; mi < 2; mi++)
#pragma unroll
        for (int nf = 0; nf < NFR; nf++) {
            float a0 = acc[mi][nf][0], a1 = acc[mi][nf][1];
            float a2 = acc[mi][nf][2], a3 = acc[mi][nf][3];
            ts[2 * mi]     += a0 + a1;  tq[2 * mi]     += a0 * a0 + a1 * a1;
            ts[2 * mi + 1] += a2 + a3;  tq[2 * mi + 1] += a2 * a2 + a3 * a3;
        }
#pragma unroll
    for (int r = 0; r < 4; r++) {
        ts[r] += __shfl_xor_sync(0xffffffffu, ts[r], 1);
        ts[r] += __shfl_xor_sync(0xffffffffu, ts[r], 2);
        tq[r] += __shfl_xor_sync(0xffffffffu, tq[r], 1);
        tq[r] += __shfl_xor_sync(0xffffffffu, tq[r], 2);
    }
    if (tg == 0) {
        const int sbase = PER_N_STATS ? n * CO : 0;
#pragma unroll
        for (int r = 0; r < 4; r++) {
            int o = o0w + (r >> 1) * 16 + g + (r & 1) * 8;
            atomicAdd(&S1[sbase + o], ts[r]);
            atomicAdd(&S2[sbase + o], tq[r]);
        }
    }
}

// ---------------- fp32 -> bf16 hi/lo split ----------------
__global__ void split_x_kernel(const float* __restrict__ src,
                               __nv_bfloat16* __restrict__ hi,
                               __nv_bfloat16* __restrict__ lo, size_t count4)
{
    size_t i = (size_t)blockIdx.x * 256 + threadIdx.x;
    if (i >= count4) return;
    float4 v = ((const float4*)src)[i];
    __nv_bfloat16 h0, h1, h2, h3, l0_, l1_, l2_, l3_;
    bf_split(v.x, h0, l0_); bf_split(v.y, h1, l1_);
    bf_split(v.z, h2, l2_); bf_split(v.w, h3, l3_);
    ((__nv_bfloat162*)hi)[2 * i]     = __nv_bfloat162(h0, h1);
    ((__nv_bfloat162*)hi)[2 * i + 1] = __nv_bfloat162(h2, h3);
    ((__nv_bfloat162*)lo)[2 * i]     = __nv_bfloat162(l0_, l1_);
    ((__nv_bfloat162*)lo)[2 * i + 1] = __nv_bfloat162(l2_, l3_);
}

// ---------------- gate + per-sample weights (bf16 hi/lo), parallel over i ----
// grid (NN, CI/16), block 128 (o). Block y==0 also zeroes the stats accums.
__global__ void gate_weights_kernel(const float* __restrict__ t,
                                    const float* __restrict__ gw,
                                    const float* __restrict__ gb,
                                    const float* __restrict__ k5,
                                    const float* __restrict__ k3,
                                    const float* __restrict__ k1,
                                    const float* __restrict__ a3,
                                    const float* __restrict__ a5,
                                    __nv_bfloat16* __restrict__ wh,
                                    __nv_bfloat16* __restrict__ wl,
                                    float* __restrict__ S1, float* __restrict__ S2,
                                    int CI)
{
    int n = blockIdx.x;
    int o = threadIdx.x;
    int HF = CI >> 6;
    if (blockIdx.y == 0) {    // zero stats for this n (consumed after this layer's conv)
        S1[n * CO + o] = 0.f;
        S2[n * CO + o] = 0.f;
    }
    float tv[TT];
#pragma unroll
    for (int j = 0; j < TT; j++) tv[j] = t[n * TT + j];
    float g[5];
    float mx = -1e30f;
#pragma unroll
    for (int e = 0; e < 5; e++) {
        float s = gb[e * CO + o];
        const float* gwr = gw + (size_t)(e * CO + o) * TT;
#pragma unroll
        for (int j = 0; j < TT; j++) s += tv[j] * gwr[j];
        g[e] = s;
        mx = fmaxf(mx, s);
    }
    float den = 0.f;
#pragma unroll
    for (int e = 0; e < 5; e++) { g[e] = expf(g[e] - mx); den += g[e]; }
    float inv = 1.f / den;
#pragma unroll
    for (int e = 0; e < 5; e++) g[e] *= inv;
    float g3 = g[3] * (1.f / 3.f);
    float g4 = g[4] * 0.2f;

    const int i_lo = blockIdx.y * 16, i_hi = i_lo + 16;
#pragma unroll 4
    for (int i = i_lo; i < i_hi; i++) {
        int oi = o * CI + i;
        const float* p5 = k5 + (size_t)oi * 5;
        const float* p3 = k3 + (size_t)oi * 3;
        float c1 = k1[oi], c3v = a3[oi], c5v = a5[oi];
        float bse = g4 * c5v;
        float wv[5];
        wv[0] = g[0] * p5[0] + bse;
        wv[1] = g[0] * p5[1] + bse;
        wv[2] = g[0] * p5[2] + g[1] * p3[0] + g3 * c3v + bse;
        wv[3] = g[0] * p5[3] + g[1] * p3[1] + g3 * c3v + bse;
        wv[4] = g[0] * p5[4] + g[1] * p3[2] + g3 * c3v + g[2] * c1 + bse;
        int hf = i >> 6, ii = i & 63;
#pragma unroll
        for (int k = 0; k < 5; k++) {
            __nv_bfloat16 h, l;
            bf_split(wv[k], h, l);
            size_t idx = ((((size_t)n * 5 + k) * HF + hf) * 128 + o) * 64 + ii;
            wh[idx] = h;
            wl[idx] = l;
        }
    }
}

// ---------------- downsample weight reorder + split (+ zero bn accums) -------
__global__ void split_dw_kernel(const float* __restrict__ dw,
                                __nv_bfloat16* __restrict__ wdh,
                                __nv_bfloat16* __restrict__ wdl,
                                float* __restrict__ B1, float* __restrict__ B2)
{
    int idx = blockIdx.x * 256 + threadIdx.x;   // CO * 256
    if (blockIdx.x == 0) {
        if (threadIdx.x < CO) B1[threadIdx.x] = 0.f;
        else B2[threadIdx.x - CO] = 0.f;
    }
    if (idx >= CO * 256) return;
    int o = idx >> 8, r = idx & 255;
    int kk = r >> 7, ifull = r & 127;
    float v = dw[(size_t)o * 256 + ifull * 2 + kk];
    __nv_bfloat16 h, l;
    bf_split(v, h, l);
    size_t out = (((size_t)kk * 2 + (ifull >> 6)) * 128 + o) * 64 + (ifull & 63);
    wdh[out] = h;
    wdl[out] = l;
}

// ---------------- finalize kernels ----------------
__global__ void inorm_finalize(const float* __restrict__ S1, const float* __restrict__ S2,
                               const float* __restrict__ gamma, const float* __restrict__ beta,
                               float* __restrict__ scale, float* __restrict__ shift)
{
    int no = blockIdx.x * 256 + threadIdx.x;
    if (no >= NN * CO) return;
    int o = no & (CO - 1);
    float mu = S1[no] * (1.f / LL);
    float var = S2[no] * (1.f / LL) - mu * mu;
    float sc = gamma[o] * rsqrtf(var + 1e-5f);
    scale[no] = sc;
    shift[no] = beta[o] - mu * sc;
}

__global__ void bn_finalize(const float* __restrict__ B1, const float* __restrict__ B2,
                            const float* __restrict__ dg, const float* __restrict__ db,
                            float* __restrict__ bs, float* __restrict__ bb)
{
    int o = threadIdx.x;
    if (o >= CO) return;
    const float cnt = (float)NN * LO;
    float mu = B1[o] / cnt;
    float var = B2[o] / cnt - mu * mu;
    float sc = dg[o] * rsqrtf(var + 1e-5f);
    bs[o] = sc;
    bb[o] = db[o] - mu * sc;
}

// ---------------- norm + mish + transpose (+ bf16 hi/lo outputs) ----------------
__global__ void norm_transpose_kernel(const float* __restrict__ y,
                                      const float* __restrict__ scale,
                                      const float* __restrict__ shift,
                                      float* __restrict__ out_full,
                                      __nv_bfloat16* __restrict__ out_hi,
                                      __nv_bfloat16* __restrict__ out_lo)
{
    __shared__ float tile[CO][33];
    __shared__ float sc[CO], sh[CO];
    int n = blockIdx.y, l0 = blockIdx.x * 32;
    int tid = threadIdx.x;
    if (tid < CO) { sc[tid] = scale[n * CO + tid]; sh[tid] = shift[n * CO + tid]; }
    __syncthreads();
    int lt = tid & 31, ob = tid >> 5;
#pragma unroll
    for (int r = 0; r < 16; r++) {
        int o = ob + 8 * r;
        float v = y[((size_t)(n * CO + o)) * LL + l0 + lt];
        tile[o][lt] = mishf(v * sc[o] + sh[o]);
    }
    __syncthreads();
    int oc = tid & 127, lb = tid >> 7;
#pragma unroll
    for (int ly = lb; ly < 32; ly += 2) {
        size_t idx = ((size_t)n * LL + l0 + ly) * CO + oc;
        float v = tile[oc][ly];
        if (out_full) out_full[idx] = v;
        __nv_bfloat16 h, l;
        bf_split(v, h, l);
        out_hi[idx] = h;
        out_lo[idx] = l;
    }
}

// ---------------- batch-norm apply ----------------
__global__ void bn_apply_kernel(const float* __restrict__ xd,
                                const float* __restrict__ bs,
                                const float* __restrict__ bb,
                                float* __restrict__ out)
{
    size_t i4 = (size_t)blockIdx.x * 256 + threadIdx.x;
    const size_t total4 = (size_t)NN * CO * LO / 4;
    if (i4 >= total4) return;
    float4 v = ((const float4*)xd)[i4];
    int o = (int)((i4 * 4 / LO) & (CO - 1));
    float sc = bs[o], sh = bb[o];
    float4 r;
    r.x = mishf(v.x * sc + sh);
    r.y = mishf(v.y * sc + sh);
    r.z = mishf(v.z * sc + sh);
    r.w = mishf(v.w * sc + sh);
    ((float4*)out)[i4] = r;
}

// ---------------- launch ----------------
extern "C" void kernel_launch(void* const* d_in, const int* in_sizes, int n_in,
                              void* d_out, int out_size)
{
    const float* x        = (const float*)d_in[0];
    const float* t        = (const float*)d_in[1];
    const float* l1_k5    = (const float*)d_in[2];
    const float* l1_k3    = (const float*)d_in[3];
    const float* l1_k1    = (const float*)d_in[4];
    const float* l1_a3    = (const float*)d_in[5];
    const float* l1_a5    = (const float*)d_in[6];
    const float* l1_gw    = (const float*)d_in[7];
    const float* l1_gb    = (const float*)d_in[8];
    const float* l1_gamma = (const float*)d_in[9];
    const float* l1_beta  = (const float*)d_in[10];
    const float* l2_k5    = (const float*)d_in[11];
    const float* l2_k3    = (const float*)d_in[12];
    const float* l2_k1    = (const float*)d_in[13];
    const float* l2_a3    = (const float*)d_in[14];
    const float* l2_a5    = (const float*)d_in[15];
    const float* l2_gw    = (const float*)d_in[16];
    const float* l2_gb    = (const float*)d_in[17];
    const float* l2_gamma = (const float*)d_in[18];
    const float* l2_beta  = (const float*)d_in[19];
    const float* dw       = (const float*)d_in[20];
    const float* dg       = (const float*)d_in[21];
    const float* db       = (const float*)d_in[22];

    float* out      = (float*)d_out;
    float* out_xd   = out;
    float* out_skip = out + (size_t)NN * CO * LO;

    __nv_bfloat16 *xh, *xl, *hh, *hl, *ssh, *ssl, *w1h, *w1l, *w2h, *w2l, *wdh, *wdl;
    float *ybuf, *xdbuf, *scl, *shf, *bsc, *bsh, *s1, *s2, *b1, *b2;
    cudaGetSymbolAddress((void**)&xh, g_xh);
    cudaGetSymbolAddress((void**)&xl, g_xl);
    cudaGetSymbolAddress((void**)&hh, g_hh);
    cudaGetSymbolAddress((void**)&hl, g_hl);
    cudaGetSymbolAddress((void**)&ssh, g_ssh);
    cudaGetSymbolAddress((void**)&ssl, g_ssl);
    cudaGetSymbolAddress((void**)&ybuf, g_y);
    cudaGetSymbolAddress((void**)&w1h, g_w1h);
    cudaGetSymbolAddress((void**)&w1l, g_w1l);
    cudaGetSymbolAddress((void**)&w2h, g_w2h);
    cudaGetSymbolAddress((void**)&w2l, g_w2l);
    cudaGetSymbolAddress((void**)&wdh, g_wdh);
    cudaGetSymbolAddress((void**)&wdl, g_wdl);
    cudaGetSymbolAddress((void**)&xdbuf, g_xd);
    cudaGetSymbolAddress((void**)&scl, g_scale);
    cudaGetSymbolAddress((void**)&shf, g_shift);
    cudaGetSymbolAddress((void**)&bsc, g_bscale);
    cudaGetSymbolAddress((void**)&bsh, g_bshift);
    cudaGetSymbolAddress((void**)&s1, g_s1);
    cudaGetSymbolAddress((void**)&s2, g_s2);
    cudaGetSymbolAddress((void**)&b1, g_b1);
    cudaGetSymbolAddress((void**)&b2, g_b2);

    // smem sizes
    const int SM1 = 2 * (260 * 144) + 4 * (128 * 144);   // 148608
    const int SM2 = 2 * (260 * 272) + 4 * (128 * 144);   // 215168
    const int SMD = 2 * (256 * 272) + 4 * (128 * 144);   // 212992
    cudaFuncSetAttribute((const void*)mma_conv<64, 5, 1, 4, 256, true>,
                         cudaFuncAttributeMaxDynamicSharedMemorySize, SM1);
    cudaFuncSetAttribute((const void*)mma_conv<128, 5, 1, 4, 256, true>,
                         cudaFuncAttributeMaxDynamicSharedMemorySize, SM2);
    cudaFuncSetAttribute((const void*)mma_conv<128, 2, 2, 0, 128, false>,
                         cudaFuncAttributeMaxDynamicSharedMemorySize, SMD);

    // x -> bf16 hi/lo
    {
        size_t c4 = (size_t)NN * LL * CI1 / 4;
        split_x_kernel<<<(int)((c4 + 255) / 256), 256>>>(x, xh, xl, c4);
    }

    // layer 1
    gate_weights_kernel<<<dim3(NN, CI1 / 16), 128>>>(t, l1_gw, l1_gb, l1_k5, l1_k3, l1_k1,
                                                     l1_a3, l1_a5, w1h, w1l, s1, s2, CI1);
    mma_conv<64, 5, 1, 4, 256, true><<<dim3(LL / 256, NN), 512, SM1>>>(
        xh, xl, w1h, w1l, ybuf, s1, s2, (size_t)LL * CI1, (size_t)5 * 1 * CO * 64, LL);
    inorm_finalize<<<(NN * CO + 255) / 256, 256>>>(s1, s2, l1_gamma, l1_beta, scl, shf);
    norm_transpose_kernel<<<dim3(LL / 32, NN), 256>>>(ybuf, scl, shf, nullptr, hh, hl);

    // layer 2
    gate_weights_kernel<<<dim3(NN, CO / 16), 128>>>(t, l2_gw, l2_gb, l2_k5, l2_k3, l2_k1,
                                                    l2_a3, l2_a5, w2h, w2l, s1, s2, CO);
    mma_conv<128, 5, 1, 4, 256, true><<<dim3(LL / 256, NN), 512, SM2>>>(
        hh, hl, w2h, w2l, ybuf, s1, s2, (size_t)LL * CO, (size_t)5 * 2 * CO * 64, LL);
    inorm_finalize<<<(NN * CO + 255) / 256, 256>>>(s1, s2, l2_gamma, l2_beta, scl, shf);
    norm_transpose_kernel<<<dim3(LL / 32, NN), 256>>>(ybuf, scl, shf, out_skip, ssh, ssl);

    // downsample + BN + mish
    split_dw_kernel<<<(CO * 256 + 255) / 256, 256>>>(dw, wdh, wdl, b1, b2);
    mma_conv<128, 2, 2, 0, 128, false><<<dim3(LO / 128, NN), 512, SMD>>>(
        ssh, ssl, wdh, wdl, xdbuf, b1, b2, (size_t)LL * CO, 0, LO);
    bn_finalize<<<1, 128>>>(b1, b2, dg, db, bsc, bsh);
    bn_apply_kernel<<<(int)(((size_t)NN * CO * LO / 4 + 255) / 256), 256>>>(xdbuf, bsc, bsh, out_xd);
}

// round 6
// speedup vs baseline: 2.9379x; 1.1993x over previous
#include <cuda_runtime.h>
#include <cuda_fp16.h>
#include <math.h>
#include <stdint.h>

#define NN 32
#define LL 8192
#define CO 128
#define CI1 64
#define TT 10
#define LO 4096

// ---------------- scratch (__device__ globals; no allocation) ----------------
__device__ __align__(128) __half g_xh[(size_t)NN * LL * CI1];
__device__ __align__(128) __half g_hh[(size_t)NN * LL * CO];
__device__ __align__(128) __half g_ssh[(size_t)NN * LL * CO];
__device__ __align__(128) float g_y[(size_t)NN * CO * LL];
__device__ __align__(128) __half g_w1h[(size_t)NN * 5 * 1 * CO * 64];
__device__ __align__(128) __half g_w1l[(size_t)NN * 5 * 1 * CO * 64];
__device__ __align__(128) __half g_w2h[(size_t)NN * 5 * 2 * CO * 64];
__device__ __align__(128) __half g_w2l[(size_t)NN * 5 * 2 * CO * 64];
__device__ __align__(128) __half g_wdh[4 * CO * 64];
__device__ __align__(128) __half g_wdl[4 * CO * 64];
__device__ __align__(128) float g_xd[(size_t)NN * CO * LO];
__device__ float g_s1[NN * CO];
__device__ float g_s2[NN * CO];
__device__ float g_b1[CO];
__device__ float g_b2[CO];
__device__ float g_scale[NN * CO];
__device__ float g_shift[NN * CO];
__device__ float g_bscale[CO];
__device__ float g_bshift[CO];

// ---------------- small device helpers ----------------
__device__ __forceinline__ float mishf(float v) {
    float sp = (v > 20.f) ? v : log1pf(expf(v));
    return v * tanhf(sp);
}
__device__ __forceinline__ uint32_t smem_u32(const void* p) {
    uint32_t a;
    asm("{ .reg .u64 t; cvta.to.shared.u64 t, %1; cvt.u32.u64 %0, t; }" : "=r"(a) : "l"(p));
    return a;
}
__device__ __forceinline__ void cp16(uint32_t dst, const void* src) {
    asm volatile("cp.async.cg.shared.global [%0], [%1], 16;" :: "r"(dst), "l"(src));
}
__device__ __forceinline__ void cp_commit() {
    asm volatile("cp.async.commit_group;" ::: "memory");
}
template <int N>
__device__ __forceinline__ void cp_wait() {
    asm volatile("cp.async.wait_group %0;" :: "n"(N) : "memory");
}
__device__ __forceinline__ void ldsm4(uint32_t* r, uint32_t addr) {
    asm volatile("ldmatrix.sync.aligned.m8n8.x4.shared.b16 {%0,%1,%2,%3}, [%4];"
                 : "=r"(r[0]), "=r"(r[1]), "=r"(r[2]), "=r"(r[3]) : "r"(addr));
}
__device__ __forceinline__ void mma_f16(float* d, const uint32_t* a, const uint32_t* b) {
    asm volatile("mma.sync.aligned.m16n8k16.row.col.f32.f16.f16.f32 "
                 "{%0,%1,%2,%3}, {%4,%5,%6,%7}, {%8,%9}, {%0,%1,%2,%3};"
                 : "+f"(d[0]), "+f"(d[1]), "+f"(d[2]), "+f"(d[3])
                 : "r"(a[0]), "r"(a[1]), "r"(a[2]), "r"(a[3]), "r"(b[0]), "r"(b[1]));
}
__device__ __forceinline__ void h_split(float v, __half& h, __half& l) {
    h = __float2half_rn(v);
    l = __float2half_rn(v - __half2float(h));
}

// ============================================================================
// Conv-as-GEMM, warp-level fp16 MMA, 2-term W-split (W = hi+lo fp16, X = fp16).
//   Y[n, o, l0+j] = sum_{k<NSHIFT, i<CI} W[n,o,i,k] * X[n, RS*(l0+j)+k-HALO, i]
// CTA 512 threads, tile M=128 (o) x NT (l). Per piece: wait -> barrier ->
// prefetch(p+1) -> MMA(p). Fused sum/sumsq stats in the epilogue.
// ============================================================================
template <int CI, int NSHIFT, int RS, int HALO, int NT, bool PER_N_STATS>
__global__ void __launch_bounds__(512)
mma_conv(const __half* __restrict__ X,
         const __half* __restrict__ Wh, const __half* __restrict__ Wl,
         float* __restrict__ Y, float* __restrict__ S1, float* __restrict__ S2,
         size_t x_nstride, size_t w_nstride, int outL)
{
    constexpr int HF = CI / 64;
    constexpr int P = NSHIFT * HF;
    constexpr int XR = NT * RS + HALO;
    constexpr int XPITCH = CI * 2 + 16;      // bytes; row step ≡ 4 banks (mod 32)
    constexpr int WPITCH = 144;
    constexpr int WCH = 128 * WPITCH;
    constexpr int XT = XR * XPITCH;
    constexpr int SEGR = CI / 8;
    constexpr int NB = NT / 64;
    constexpr int NFR = 2 * NB;

    extern __shared__ char sm[];
    const uint32_t base = smem_u32(sm);
    const uint32_t x_s = base;
    const uint32_t w_s = base + XT;

    const int tid = threadIdx.x;
    const int n = blockIdx.y;
    const int l0 = blockIdx.x * NT;

    if (HALO > 0 && blockIdx.x == 0) {
        const uint4 z = make_uint4(0, 0, 0, 0);
        for (int s = tid; s < HALO * SEGR; s += 512) {
            int r = s / SEGR, c = s % SEGR;
            *(uint4*)(sm + r * XPITCH + c * 16) = z;
        }
    }
    {   // X tile
        const __half* gx = X + (size_t)n * x_nstride;
        for (int s = tid; s < XR * SEGR; s += 512) {
            int r = s / SEGR, c = s % SEGR;
            long l = (long)l0 * RS - HALO + r;
            if (l >= 0)
                cp16(x_s + r * XPITCH + c * 16, gx + (size_t)l * CI + (size_t)c * 8);
        }
    }
    {   // W piece 0 (hi | lo)
        const __half* ph = Wh + (size_t)n * w_nstride;
        const __half* pl = Wl + (size_t)n * w_nstride;
        for (int s = tid; s < 1024; s += 512) {
            int r = s >> 3, c = s & 7;
            cp16(w_s + r * WPITCH + c * 16, ph + r * 64 + c * 8);
            cp16(w_s + WCH + r * WPITCH + c * 16, pl + r * 64 + c * 8);
        }
    }
    cp_commit();

    const int warp = tid >> 5, lane = tid & 31;
    const int o0w = (warp >> 2) * 32, n0w = (warp & 3) * (NT / 4);
    const int a_row = (lane & 7) + ((lane >> 3) & 1) * 8;
    const int a_csh = (lane >> 4) * 8;
    const int b_jj = (lane & 7) + ((lane >> 4) << 3);
    const int b_csh = ((lane >> 3) & 1) * 8;

    float acc[2][NFR][4];
#pragma unroll
    for (int mi = 0; mi < 2; mi++)
#pragma unroll
        for (int nf = 0; nf < NFR; nf++)
#pragma unroll
            for (int q = 0; q < 4; q++) acc[mi][nf][q] = 0.f;

    for (int p = 0; p < P; p++) {
        cp_wait<0>();
        __syncthreads();   // everyone done reading buffer (p+1)&1 (= piece p-1)
        if (p + 1 < P) {
            const int b = (p + 1) & 1;
            const __half* ph = Wh + (size_t)n * w_nstride + (size_t)(p + 1) * 8192;
            const __half* pl = Wl + (size_t)n * w_nstride + (size_t)(p + 1) * 8192;
            for (int s = tid; s < 1024; s += 512) {
                int r = s >> 3, c = s & 7;
                cp16(w_s + b * 2 * WCH + r * WPITCH + c * 16, ph + r * 64 + c * 8);
                cp16(w_s + b * 2 * WCH + WCH + r * WPITCH + c * 16, pl + r * 64 + c * 8);
            }
            cp_commit();
        }

        const int k = p / HF, hf = p % HF;
        const uint32_t wh_b = w_s + (uint32_t)(p & 1) * (2 * WCH);
        const uint32_t wl_b = wh_b + WCH;

#pragma unroll
        for (int i16 = 0; i16 < 4; i16++) {
            const int i0 = i16 * 16;
            uint32_t Ah[2][4], Al[2][4];
#pragma unroll
            for (int mi = 0; mi < 2; mi++) {
                uint32_t ao = (uint32_t)((o0w + a_row + mi * 16) * WPITCH + (i0 + a_csh) * 2);
                ldsm4(Ah[mi], wh_b + ao);
                ldsm4(Al[mi], wl_b + ao);
            }
            const int xcol = (hf * 64 + i0 + b_csh) * 2;
#pragma unroll
            for (int nb = 0; nb < NB; nb++) {
                uint32_t B[4];
                uint32_t xo = (uint32_t)((RS * (n0w + nb * 16 + b_jj) + k) * XPITCH + xcol);
                ldsm4(B, x_s + xo);
#pragma unroll
                for (int mi = 0; mi < 2; mi++)
#pragma unroll
                    for (int hl = 0; hl < 2; hl++) {
                        float* d = acc[mi][nb * 2 + hl];
                        mma_f16(d, Ah[mi], &B[hl * 2]);
                        mma_f16(d, Al[mi], &B[hl * 2]);
                    }
            }
        }
    }

    // ---------------- epilogue: store + fused stats ----------------
    const int g = lane >> 2, tg = lane & 3;
#pragma unroll
    for (int mi = 0; mi < 2; mi++) {
        const int o = o0w + mi * 16 + g;
        float* row0 = Y + ((size_t)(n * CO + o)) * outL + l0 + n0w;
        float* row1 = row0 + (size_t)8 * outL;
#pragma unroll
        for (int nf = 0; nf < NFR; nf++) {
            int c = nf * 8 + tg * 2;
            *(float2*)(row0 + c) = make_float2(acc[mi][nf][0], acc[mi][nf][1]);
            *(float2*)(row1 + c) = make_float2(acc[mi][nf][2], acc[mi][nf][3]);
        }
    }
    float ts[4], tq[4];
#pragma unroll
    for (int r = 0; r < 4; r++) { ts[r] = 0.f; tq[r] = 0.f; }
#pragma unroll
    for (int mi = 0; mi < 2; mi++)
#pragma unroll
        for (int nf = 0; nf < NFR; nf++) {
            float a0 = acc[mi][nf][0], a1 = acc[mi][nf][1];
            float a2 = acc[mi][nf][2], a3 = acc[mi][nf][3];
            ts[2 * mi]     += a0 + a1;  tq[2 * mi]     += a0 * a0 + a1 * a1;
            ts[2 * mi + 1] += a2 + a3;  tq[2 * mi + 1] += a2 * a2 + a3 * a3;
        }
#pragma unroll
    for (int r = 0; r < 4; r++) {
        ts[r] += __shfl_xor_sync(0xffffffffu, ts[r], 1);
        ts[r] += __shfl_xor_sync(0xffffffffu, ts[r], 2);
        tq[r] += __shfl_xor_sync(0xffffffffu, tq[r], 1);
        tq[r] += __shfl_xor_sync(0xffffffffu, tq[r], 2);
    }
    if (tg == 0) {
        const int sbase = PER_N_STATS ? n * CO : 0;
#pragma unroll
        for (int r = 0; r < 4; r++) {
            int o = o0w + (r >> 1) * 16 + g + (r & 1) * 8;
            atomicAdd(&S1[sbase + o], ts[r]);
            atomicAdd(&S2[sbase + o], tq[r]);
        }
    }
}

// ---------------- fp32 -> fp16 ----------------
__global__ void split_x_kernel(const float* __restrict__ src,
                               __half* __restrict__ hi, size_t count4)
{
    size_t i = (size_t)blockIdx.x * 256 + threadIdx.x;
    if (i >= count4) return;
    float4 v = ((const float4*)src)[i];
    ((__half2*)hi)[2 * i]     = __floats2half2_rn(v.x, v.y);
    ((__half2*)hi)[2 * i + 1] = __floats2half2_rn(v.z, v.w);
}

// ---------------- gate + per-sample weights (fp16 hi/lo), parallel over i ----
__global__ void gate_weights_kernel(const float* __restrict__ t,
                                    const float* __restrict__ gw,
                                    const float* __restrict__ gb,
                                    const float* __restrict__ k5,
                                    const float* __restrict__ k3,
                                    const float* __restrict__ k1,
                                    const float* __restrict__ a3,
                                    const float* __restrict__ a5,
                                    __half* __restrict__ wh,
                                    __half* __restrict__ wl,
                                    float* __restrict__ S1, float* __restrict__ S2,
                                    int CI)
{
    int n = blockIdx.x;
    int o = threadIdx.x;
    int HF = CI >> 6;
    if (blockIdx.y == 0) {
        S1[n * CO + o] = 0.f;
        S2[n * CO + o] = 0.f;
    }
    float tv[TT];
#pragma unroll
    for (int j = 0; j < TT; j++) tv[j] = t[n * TT + j];
    float g[5];
    float mx = -1e30f;
#pragma unroll
    for (int e = 0; e < 5; e++) {
        float s = gb[e * CO + o];
        const float* gwr = gw + (size_t)(e * CO + o) * TT;
#pragma unroll
        for (int j = 0; j < TT; j++) s += tv[j] * gwr[j];
        g[e] = s;
        mx = fmaxf(mx, s);
    }
    float den = 0.f;
#pragma unroll
    for (int e = 0; e < 5; e++) { g[e] = expf(g[e] - mx); den += g[e]; }
    float inv = 1.f / den;
#pragma unroll
    for (int e = 0; e < 5; e++) g[e] *= inv;
    float g3 = g[3] * (1.f / 3.f);
    float g4 = g[4] * 0.2f;

    const int i_lo = blockIdx.y * 16, i_hi = i_lo + 16;
#pragma unroll 4
    for (int i = i_lo; i < i_hi; i++) {
        int oi = o * CI + i;
        const float* p5 = k5 + (size_t)oi * 5;
        const float* p3 = k3 + (size_t)oi * 3;
        float c1 = k1[oi], c3v = a3[oi], c5v = a5[oi];
        float bse = g4 * c5v;
        float wv[5];
        wv[0] = g[0] * p5[0] + bse;
        wv[1] = g[0] * p5[1] + bse;
        wv[2] = g[0] * p5[2] + g[1] * p3[0] + g3 * c3v + bse;
        wv[3] = g[0] * p5[3] + g[1] * p3[1] + g3 * c3v + bse;
        wv[4] = g[0] * p5[4] + g[1] * p3[2] + g3 * c3v + g[2] * c1 + bse;
        int hf = i >> 6, ii = i & 63;
#pragma unroll
        for (int k = 0; k < 5; k++) {
            __half h, l;
            h_split(wv[k], h, l);
            size_t idx = ((((size_t)n * 5 + k) * HF + hf) * 128 + o) * 64 + ii;
            wh[idx] = h;
            wl[idx] = l;
        }
    }
}

// ---------------- downsample weight reorder + split (+ zero bn accums) -------
__global__ void split_dw_kernel(const float* __restrict__ dw,
                                __half* __restrict__ wdh,
                                __half* __restrict__ wdl,
                                float* __restrict__ B1, float* __restrict__ B2)
{
    int idx = blockIdx.x * 256 + threadIdx.x;
    if (blockIdx.x == 0) {
        if (threadIdx.x < CO) B1[threadIdx.x] = 0.f;
        else B2[threadIdx.x - CO] = 0.f;
    }
    if (idx >= CO * 256) return;
    int o = idx >> 8, r = idx & 255;
    int kk = r >> 7, ifull = r & 127;
    float v = dw[(size_t)o * 256 + ifull * 2 + kk];
    __half h, l;
    h_split(v, h, l);
    size_t out = (((size_t)kk * 2 + (ifull >> 6)) * 128 + o) * 64 + (ifull & 63);
    wdh[out] = h;
    wdl[out] = l;
}

// ---------------- finalize kernels ----------------
__global__ void inorm_finalize(const float* __restrict__ S1, const float* __restrict__ S2,
                               const float* __restrict__ gamma, const float* __restrict__ beta,
                               float* __restrict__ scale, float* __restrict__ shift)
{
    int no = blockIdx.x * 256 + threadIdx.x;
    if (no >= NN * CO) return;
    int o = no & (CO - 1);
    float mu = S1[no] * (1.f / LL);
    float var = S2[no] * (1.f / LL) - mu * mu;
    float sc = gamma[o] * rsqrtf(var + 1e-5f);
    scale[no] = sc;
    shift[no] = beta[o] - mu * sc;
}

__global__ void bn_finalize(const float* __restrict__ B1, const float* __restrict__ B2,
                            const float* __restrict__ dg, const float* __restrict__ db,
                            float* __restrict__ bs, float* __restrict__ bb)
{
    int o = threadIdx.x;
    if (o >= CO) return;
    const float cnt = (float)NN * LO;
    float mu = B1[o] / cnt;
    float var = B2[o] / cnt - mu * mu;
    float sc = dg[o] * rsqrtf(var + 1e-5f);
    bs[o] = sc;
    bb[o] = db[o] - mu * sc;
}

// ---------------- norm + mish + transpose (fp16 out, optional fp32 out) ------
__global__ void norm_transpose_kernel(const float* __restrict__ y,
                                      const float* __restrict__ scale,
                                      const float* __restrict__ shift,
                                      float* __restrict__ out_full,
                                      __half* __restrict__ out_hi)
{
    __shared__ float tile[CO][33];
    __shared__ float sc[CO], sh[CO];
    int n = blockIdx.y, l0 = blockIdx.x * 32;
    int tid = threadIdx.x;
    if (tid < CO) { sc[tid] = scale[n * CO + tid]; sh[tid] = shift[n * CO + tid]; }
    __syncthreads();
    int lt = tid & 31, ob = tid >> 5;
#pragma unroll
    for (int r = 0; r < 16; r++) {
        int o = ob + 8 * r;
        float v = y[((size_t)(n * CO + o)) * LL + l0 + lt];
        tile[o][lt] = mishf(v * sc[o] + sh[o]);
    }
    __syncthreads();
    int oc = tid & 127, lb = tid >> 7;
#pragma unroll
    for (int ly = lb; ly < 32; ly += 2) {
        size_t idx = ((size_t)n * LL + l0 + ly) * CO + oc;
        float v = tile[oc][ly];
        if (out_full) out_full[idx] = v;
        out_hi[idx] = __float2half_rn(v);
    }
}

// ---------------- batch-norm apply ----------------
__global__ void bn_apply_kernel(const float* __restrict__ xd,
                                const float* __restrict__ bs,
                                const float* __restrict__ bb,
                                float* __restrict__ out)
{
    size_t i4 = (size_t)blockIdx.x * 256 + threadIdx.x;
    const size_t total4 = (size_t)NN * CO * LO / 4;
    if (i4 >= total4) return;
    float4 v = ((const float4*)xd)[i4];
    int o = (int)((i4 * 4 / LO) & (CO - 1));
    float sc = bs[o], sh = bb[o];
    float4 r;
    r.x = mishf(v.x * sc + sh);
    r.y = mishf(v.y * sc + sh);
    r.z = mishf(v.z * sc + sh);
    r.w = mishf(v.w * sc + sh);
    ((float4*)out)[i4] = r;
}

// ---------------- launch ----------------
extern "C" void kernel_launch(void* const* d_in, const int* in_sizes, int n_in,
                              void* d_out, int out_size)
{
    const float* x        = (const float*)d_in[0];
    const float* t        = (const float*)d_in[1];
    const float* l1_k5    = (const float*)d_in[2];
    const float* l1_k3    = (const float*)d_in[3];
    const float* l1_k1    = (const float*)d_in[4];
    const float* l1_a3    = (const float*)d_in[5];
    const float* l1_a5    = (const float*)d_in[6];
    const float* l1_gw    = (const float*)d_in[7];
    const float* l1_gb    = (const float*)d_in[8];
    const float* l1_gamma = (const float*)d_in[9];
    const float* l1_beta  = (const float*)d_in[10];
    const float* l2_k5    = (const float*)d_in[11];
    const float* l2_k3    = (const float*)d_in[12];
    const float* l2_k1    = (const float*)d_in[13];
    const float* l2_a3    = (const float*)d_in[14];
    const float* l2_a5    = (const float*)d_in[15];
    const float* l2_gw    = (const float*)d_in[16];
    const float* l2_gb    = (const float*)d_in[17];
    const float* l2_gamma = (const float*)d_in[18];
    const float* l2_beta  = (const float*)d_in[19];
    const float* dw       = (const float*)d_in[20];
    const float* dg       = (const float*)d_in[21];
    const float* db       = (const float*)d_in[22];

    float* out      = (float*)d_out;
    float* out_xd   = out;
    float* out_skip = out + (size_t)NN * CO * LO;

    __half *xh, *hh, *ssh, *w1h, *w1l, *w2h, *w2l, *wdh, *wdl;
    float *ybuf, *xdbuf, *scl, *shf, *bsc, *bsh, *s1, *s2, *b1, *b2;
    cudaGetSymbolAddress((void**)&xh, g_xh);
    cudaGetSymbolAddress((void**)&hh, g_hh);
    cudaGetSymbolAddress((void**)&ssh, g_ssh);
    cudaGetSymbolAddress((void**)&ybuf, g_y);
    cudaGetSymbolAddress((void**)&w1h, g_w1h);
    cudaGetSymbolAddress((void**)&w1l, g_w1l);
    cudaGetSymbolAddress((void**)&w2h, g_w2h);
    cudaGetSymbolAddress((void**)&w2l, g_w2l);
    cudaGetSymbolAddress((void**)&wdh, g_wdh);
    cudaGetSymbolAddress((void**)&wdl, g_wdl);
    cudaGetSymbolAddress((void**)&xdbuf, g_xd);
    cudaGetSymbolAddress((void**)&scl, g_scale);
    cudaGetSymbolAddress((void**)&shf, g_shift);
    cudaGetSymbolAddress((void**)&bsc, g_bscale);
    cudaGetSymbolAddress((void**)&bsh, g_bshift);
    cudaGetSymbolAddress((void**)&s1, g_s1);
    cudaGetSymbolAddress((void**)&s2, g_s2);
    cudaGetSymbolAddress((void**)&b1, g_b1);
    cudaGetSymbolAddress((void**)&b2, g_b2);

    // smem sizes: XT + 4 * (128*144)
    const int SM1 = 260 * 144 + 4 * 18432;   // 111168
    const int SM2 = 260 * 272 + 4 * 18432;   // 144448
    const int SMD = 256 * 272 + 4 * 18432;   // 143360
    cudaFuncSetAttribute((const void*)mma_conv<64, 5, 1, 4, 256, true>,
                         cudaFuncAttributeMaxDynamicSharedMemorySize, SM1);
    cudaFuncSetAttribute((const void*)mma_conv<128, 5, 1, 4, 256, true>,
                         cudaFuncAttributeMaxDynamicSharedMemorySize, SM2);
    cudaFuncSetAttribute((const void*)mma_conv<128, 2, 2, 0, 128, false>,
                         cudaFuncAttributeMaxDynamicSharedMemorySize, SMD);

    // x -> fp16
    {
        size_t c4 = (size_t)NN * LL * CI1 / 4;
        split_x_kernel<<<(int)((c4 + 255) / 256), 256>>>(x, xh, c4);
    }

    // layer 1
    gate_weights_kernel<<<dim3(NN, CI1 / 16), 128>>>(t, l1_gw, l1_gb, l1_k5, l1_k3, l1_k1,
                                                     l1_a3, l1_a5, w1h, w1l, s1, s2, CI1);
    mma_conv<64, 5, 1, 4, 256, true><<<dim3(LL / 256, NN), 512, SM1>>>(
        xh, w1h, w1l, ybuf, s1, s2, (size_t)LL * CI1, (size_t)5 * 1 * CO * 64, LL);
    inorm_finalize<<<(NN * CO + 255) / 256, 256>>>(s1, s2, l1_gamma, l1_beta, scl, shf);
    norm_transpose_kernel<<<dim3(LL / 32, NN), 256>>>(ybuf, scl, shf, nullptr, hh);

    // layer 2
    gate_weights_kernel<<<dim3(NN, CO / 16), 128>>>(t, l2_gw, l2_gb, l2_k5, l2_k3, l2_k1,
                                                    l2_a3, l2_a5, w2h, w2l, s1, s2, CO);
    mma_conv<128, 5, 1, 4, 256, true><<<dim3(LL / 256, NN), 512, SM2>>>(
        hh, w2h, w2l, ybuf, s1, s2, (size_t)LL * CO, (size_t)5 * 2 * CO * 64, LL);
    inorm_finalize<<<(NN * CO + 255) / 256, 256>>>(s1, s2, l2_gamma, l2_beta, scl, shf);
    norm_transpose_kernel<<<dim3(LL / 32, NN), 256>>>(ybuf, scl, shf, out_skip, ssh);

    // downsample + BN + mish
    split_dw_kernel<<<(CO * 256 + 255) / 256, 256>>>(dw, wdh, wdl, b1, b2);
    mma_conv<128, 2, 2, 0, 128, false><<<dim3(LO / 128, NN), 512, SMD>>>(
        ssh, wdh, wdl, xdbuf, b1, b2, (size_t)LL * CO, 0, LO);
    bn_finalize<<<1, 128>>>(b1, b2, dg, db, bsc, bsh);
    bn_apply_kernel<<<(int)(((size_t)NN * CO * LO / 4 + 255) / 256), 256>>>(xdbuf, bsc, bsh, out_xd);
}